// round 16
// baseline (speedup 1.0000x reference)
#include <cuda_runtime.h>
#include <cuda_fp16.h>
#include <math.h>
#include <stdint.h>

// ---------------- problem constants ----------------
#define Bv   16
#define Sv   256
#define Tv   2048
#define Dv   512
#define Hv   8
#define DHv  64
#define Lv   6
#define FFv  2048
#define NMv  80
#define NTOK (Bv*Sv)            // 4096 tokens

// ---------------- scratch (no allocs allowed) ----------------
__device__ float g_x   [NTOK*Dv];
__device__ float g_qkv [NTOK*3*Dv];
__device__ float g_attn[NTOK*Dv];
__device__ float g_tmp [NTOK*Dv];
__device__ float g_big [NTOK*FFv];
__device__ float g_durh[NTOK*256];
__device__ float g_mels[NTOK*NMv];
__device__ float g_inv [NMv];
__device__ int   g_idx [Bv*Tv];
// transposed weights ([N,K] K-major, single fp16)
__device__ __half g_qkvT[Lv*3*Dv*Dv];
__device__ __half g_WoT [Lv*Dv*Dv];
__device__ __half g_W1T [Lv*FFv*Dv];
__device__ __half g_W2T [Lv*Dv*FFv];
__device__ __half g_m1T [FFv*Dv];
__device__ __half g_m2T [NMv*FFv];
__device__ __half g_d1T [256*Dv];

// ---------------- low-level helpers ----------------
__device__ __forceinline__ uint32_t smem_u32(const void* p) {
    uint32_t a;
    asm("{ .reg .u64 t; cvta.to.shared.u64 t, %1; cvt.u32.u64 %0, t; }" : "=r"(a) : "l"(p));
    return a;
}
__device__ __forceinline__ void ldsm4(uint32_t& a0, uint32_t& a1, uint32_t& a2,
                                      uint32_t& a3, uint32_t addr) {
    asm volatile("ldmatrix.sync.aligned.m8n8.x4.shared.b16 {%0,%1,%2,%3}, [%4];"
                 : "=r"(a0), "=r"(a1), "=r"(a2), "=r"(a3) : "r"(addr));
}
__device__ __forceinline__ void ldsm2(uint32_t& b0, uint32_t& b1, uint32_t addr) {
    asm volatile("ldmatrix.sync.aligned.m8n8.x2.shared.b16 {%0,%1}, [%2];"
                 : "=r"(b0), "=r"(b1) : "r"(addr));
}
__device__ __forceinline__ void mma_f16(float* c, const uint32_t* a,
                                        uint32_t b0, uint32_t b1) {
    asm volatile("mma.sync.aligned.m16n8k16.row.col.f32.f16.f16.f32 "
                 "{%0,%1,%2,%3}, {%4,%5,%6,%7}, {%8,%9}, {%0,%1,%2,%3};"
                 : "+f"(c[0]), "+f"(c[1]), "+f"(c[2]), "+f"(c[3])
                 : "r"(a[0]), "r"(a[1]), "r"(a[2]), "r"(a[3]), "r"(b0), "r"(b1));
}
__device__ __forceinline__ void cpa16(uint32_t dst, const void* src, int sz) {
    asm volatile("cp.async.cg.shared.global [%0], [%1], 16, %2;"
                 :: "r"(dst), "l"(src), "r"(sz) : "memory");
}
#define CPA_COMMIT() asm volatile("cp.async.commit_group;" ::: "memory")
#define CPA_WAIT1()  asm volatile("cp.async.wait_group 1;" ::: "memory")

// split two fp32 into packed fp16x2 hi + fp16x2 lo
__device__ __forceinline__ void split2h(float x, float y, uint32_t& hi, uint32_t& lo) {
    __half2 h = __floats2half2_rn(x, y);
    float hx = __low2float(h);
    float hy = __high2float(h);
    __half2 l2 = __floats2half2_rn(x - hx, y - hy);
    hi = *(uint32_t*)&h;
    lo = *(uint32_t*)&l2;
}
__device__ __forceinline__ uint32_t packh2(float x, float y) {
    __half2 h = __floats2half2_rn(x, y);
    return *(uint32_t*)&h;
}

// ================= split-fp16 mma.sync GEMM (2-term, 3-stage, 1 sync/iter) ======
// EPI: 0 none, 1 bias, 2 bias+relu, 3 bias+residual (Rres same shape as C)
#define RSB     80u
#define TILE_A  (128u*RSB)

template<int NT_, int EPI>
__global__ void __launch_bounds__(256, 1)
mgemm_k(const float* __restrict__ A,
        const __half* __restrict__ Bt,
        const float* __restrict__ bias, const float* __restrict__ Rres,
        float* __restrict__ C,
        int M, int N, int K)
{
    constexpr uint32_t TILE_BN = (uint32_t)NT_ * RSB;
    constexpr uint32_t STAGE = 2u * TILE_A + TILE_BN;   // A_hi | A_lo | B
    constexpr int NI = NT_ / 16;
    extern __shared__ char smem[];
    uint32_t sb = smem_u32(smem);
    int tid = threadIdx.x, wid = tid >> 5, l = tid & 31;
    int m0 = blockIdx.y * 128, n0 = blockIdx.x * NT_;
    int wm = (wid & 3) * 32, wn = (wid >> 2) * (NT_ / 2);

    float acc[2][NI][4];
    #pragma unroll
    for (int mi = 0; mi < 2; mi++)
        #pragma unroll
        for (int ni = 0; ni < NI; ni++)
            #pragma unroll
            for (int q = 0; q < 4; q++) acc[mi][ni][q] = 0.f;

    int ar_ = tid >> 3, ac_ = tid & 7;    // A: 32 rows x 8 col-groups (x4 rows)
    int brow = tid >> 2, bch = tid & 3;   // B: cp.async row/chunk

    float4 ard[4];
    const int NT = K / 32;

    auto loadA = [&](int kt) {
        int k0 = kt * 32;
        #pragma unroll
        for (int i = 0; i < 4; i++)
            ard[i] = *(const float4*)(A + (size_t)(m0 + ar_ + i * 32) * K + k0 + ac_ * 4);
    };
    auto storeA = [&](int s) {
        char* dst = smem + (uint32_t)s * STAGE;
        #pragma unroll
        for (int i = 0; i < 4; i++) {
            uint32_t h0, h1, l0, l1;
            split2h(ard[i].x, ard[i].y, h0, l0);
            split2h(ard[i].z, ard[i].w, h1, l1);
            uint32_t off = (uint32_t)(ar_ + i * 32) * RSB + ac_ * 8u;
            *(uint2*)(dst + off)          = make_uint2(h0, h1);
            *(uint2*)(dst + TILE_A + off) = make_uint2(l0, l1);
        }
    };
    auto cpaB = [&](int kt, int s) {
        uint32_t bbase = sb + (uint32_t)s * STAGE + 2u * TILE_A;
        int k0 = kt * 32;
        #pragma unroll
        for (int i = 0; i < NT_ / 64; i++) {
            int row = brow + i * 64;
            int nr = n0 + row;
            int ok  = (nr < N) ? 16 : 0;
            int nrc = (nr < N) ? nr : 0;
            cpa16(bbase + (uint32_t)row * RSB + (uint32_t)bch * 16u,
                  Bt + (size_t)nrc * K + k0 + bch * 8, ok);
        }
    };

    // prologue: stages 0, 1
    loadA(0); storeA(0); cpaB(0, 0); CPA_COMMIT();
    if (NT > 1) { loadA(1); storeA(1); cpaB(1, 1); }
    CPA_COMMIT();

    uint32_t aoff = (uint32_t)(wm + (l & 15)) * RSB + (uint32_t)(l >> 4) * 16u;
    uint32_t boff = (uint32_t)(wn + (l & 7)) * RSB + (uint32_t)((l >> 3) & 1) * 16u;

    int s_cur = 0, s_pf = 2;   // stage being computed / stage being prefetched
    for (int kt = 0; kt < NT; kt++) {
        CPA_WAIT1();
        __syncthreads();
        bool pf = (kt + 2 < NT);
        if (pf) { loadA(kt + 2); cpaB(kt + 2, s_pf); }
        CPA_COMMIT();

        // compute on stage s_cur
        {
            uint32_t aH_ = sb + (uint32_t)s_cur * STAGE;
            uint32_t aL_ = aH_ + TILE_A;
            uint32_t bB_ = aH_ + 2 * TILE_A;
            #pragma unroll
            for (int ks = 0; ks < 2; ks++) {
                uint32_t ah[2][4], al[2][4];
                #pragma unroll
                for (int mi = 0; mi < 2; mi++) {
                    uint32_t ad = aoff + (uint32_t)mi * 16u * RSB + (uint32_t)ks * 32u;
                    ldsm4(ah[mi][0], ah[mi][1], ah[mi][2], ah[mi][3], aH_ + ad);
                    ldsm4(al[mi][0], al[mi][1], al[mi][2], al[mi][3], aL_ + ad);
                }
                #pragma unroll
                for (int ni = 0; ni < NI; ni++) {
                    uint32_t bd = boff + (uint32_t)ni * 8u * RSB + (uint32_t)ks * 32u;
                    uint32_t b0, b1;
                    ldsm2(b0, b1, bB_ + bd);
                    #pragma unroll
                    for (int mi = 0; mi < 2; mi++) {
                        mma_f16(acc[mi][ni], ah[mi], b0, b1);
                        mma_f16(acc[mi][ni], al[mi], b0, b1);
                    }
                }
            }
        }
        if (pf) storeA(s_pf);
        s_cur = (s_cur == 2) ? 0 : s_cur + 1;
        s_pf  = (s_pf  == 2) ? 0 : s_pf  + 1;
    }

    // epilogue
    int r_lo = l >> 2, cpair = (l & 3) * 2;
    #pragma unroll
    for (int mi = 0; mi < 2; mi++) {
        int gr0 = m0 + wm + mi * 16 + r_lo;
        #pragma unroll
        for (int ni = 0; ni < NI; ni++) {
            int gc = n0 + wn + ni * 8 + cpair;
            if (gc < N) {
                float b0 = 0.f, b1 = 0.f;
                if (EPI >= 1) { b0 = bias[gc]; b1 = bias[gc + 1]; }
                float v0 = acc[mi][ni][0] + b0, v1 = acc[mi][ni][1] + b1;
                float v2 = acc[mi][ni][2] + b0, v3 = acc[mi][ni][3] + b1;
                if (EPI == 2) {
                    v0 = fmaxf(v0, 0.f); v1 = fmaxf(v1, 0.f);
                    v2 = fmaxf(v2, 0.f); v3 = fmaxf(v3, 0.f);
                }
                if (EPI == 3) {
                    float2 r0 = *(const float2*)(Rres + (size_t)gr0 * N + gc);
                    float2 r1 = *(const float2*)(Rres + (size_t)(gr0 + 8) * N + gc);
                    v0 += r0.x; v1 += r0.y; v2 += r1.x; v3 += r1.y;
                }
                *(float2*)(C + (size_t)gr0 * N + gc)       = make_float2(v0, v1);
                *(float2*)(C + (size_t)(gr0 + 8) * N + gc) = make_float2(v2, v3);
            }
        }
    }
}

// ================= tensor-core flash attention ==================================
#define QROW 144u
#define VROW 528u
#define SM_QH 0u
#define SM_QL 36864u
#define SM_KH 73728u
#define SM_KL 110592u
#define SM_VT 147456u
#define SM_ATT (147456 + 64*528)

__global__ void __launch_bounds__(256, 1)
fattn_k(const float* __restrict__ qkv, const int* __restrict__ lens,
        float* __restrict__ o)
{
    extern __shared__ char smem[];
    uint32_t sb = smem_u32(smem);
    int h = blockIdx.x, b = blockIdx.y;
    int tid = threadIdx.x, wid = tid >> 5, l = tid & 31;
    int len = lens[b];

    {
        const float* base = qkv + (size_t)b * Sv * (3 * Dv);
        const float4* qrow = (const float4*)(base + (size_t)tid * 3 * Dv + h * DHv);
        const float4* krow = (const float4*)(base + (size_t)tid * 3 * Dv + Dv + h * DHv);
        const float4* vrow = (const float4*)(base + (size_t)tid * 3 * Dv + 2 * Dv + h * DHv);
        uint32_t qd = (uint32_t)tid * QROW;
        #pragma unroll
        for (int i = 0; i < 16; i++) {
            float4 q = qrow[i];
            q.x *= 0.125f; q.y *= 0.125f; q.z *= 0.125f; q.w *= 0.125f;
            uint32_t h0, h1, l0, l1;
            split2h(q.x, q.y, h0, l0);
            split2h(q.z, q.w, h1, l1);
            *(uint2*)(smem + qd + SM_QH + i * 8u) = make_uint2(h0, h1);
            *(uint2*)(smem + qd + SM_QL + i * 8u) = make_uint2(l0, l1);
            float4 k = krow[i];
            split2h(k.x, k.y, h0, l0);
            split2h(k.z, k.w, h1, l1);
            *(uint2*)(smem + qd + SM_KH + i * 8u) = make_uint2(h0, h1);
            *(uint2*)(smem + qd + SM_KL + i * 8u) = make_uint2(l0, l1);
            float4 v = vrow[i];
            __half* vt = (__half*)(smem + SM_VT);
            vt[(4*i+0) * (VROW/2) + tid] = __float2half_rn(v.x);
            vt[(4*i+1) * (VROW/2) + tid] = __float2half_rn(v.y);
            vt[(4*i+2) * (VROW/2) + tid] = __float2half_rn(v.z);
            vt[(4*i+3) * (VROW/2) + tid] = __float2half_rn(v.w);
        }
    }
    __syncthreads();

    int wq = wid * 32;
    float mrow[2][2], lrow[2][2];
    #pragma unroll
    for (int mi = 0; mi < 2; mi++) { mrow[mi][0] = -1e9f; mrow[mi][1] = -1e9f;
                                     lrow[mi][0] = 0.f;   lrow[mi][1] = 0.f; }
    float acc_o[2][8][4];
    #pragma unroll
    for (int mi = 0; mi < 2; mi++)
        #pragma unroll
        for (int ni = 0; ni < 8; ni++)
            #pragma unroll
            for (int q = 0; q < 4; q++) acc_o[mi][ni][q] = 0.f;

    for (int kc = 0; kc < 4; kc++) {
        int kbase = kc * 64;
        if (kbase >= len) break;

        float s_[2][8][4];
        #pragma unroll
        for (int mi = 0; mi < 2; mi++)
            #pragma unroll
            for (int ni = 0; ni < 8; ni++)
                #pragma unroll
                for (int q = 0; q < 4; q++) s_[mi][ni][q] = 0.f;

        #pragma unroll
        for (int kst = 0; kst < 4; kst++) {
            uint32_t qh[2][4], ql[2][4];
            #pragma unroll
            for (int mi = 0; mi < 2; mi++) {
                uint32_t ad = (uint32_t)(wq + mi * 16 + (l & 15)) * QROW
                            + (uint32_t)(l >> 4) * 16u + (uint32_t)kst * 32u;
                ldsm4(qh[mi][0], qh[mi][1], qh[mi][2], qh[mi][3], sb + SM_QH + ad);
                ldsm4(ql[mi][0], ql[mi][1], ql[mi][2], ql[mi][3], sb + SM_QL + ad);
            }
            #pragma unroll
            for (int ni = 0; ni < 8; ni++) {
                uint32_t kd = (uint32_t)(kbase + ni * 8 + (l & 7)) * QROW
                            + (uint32_t)((l >> 3) & 1) * 16u + (uint32_t)kst * 32u;
                uint32_t kh0, kh1, kl0, kl1;
                ldsm2(kh0, kh1, sb + SM_KH + kd);
                ldsm2(kl0, kl1, sb + SM_KL + kd);
                #pragma unroll
                for (int mi = 0; mi < 2; mi++) {
                    mma_f16(s_[mi][ni], qh[mi], kh0, kh1);
                    mma_f16(s_[mi][ni], ql[mi], kh0, kh1);
                    mma_f16(s_[mi][ni], qh[mi], kl0, kl1);
                }
            }
        }

        int kcol = kbase + (l & 3) * 2;
        #pragma unroll
        for (int mi = 0; mi < 2; mi++)
            #pragma unroll
            for (int ni = 0; ni < 8; ni++) {
                int k0 = kcol + ni * 8;
                if (k0 >= len)     { s_[mi][ni][0] = -1e9f; s_[mi][ni][2] = -1e9f; }
                if (k0 + 1 >= len) { s_[mi][ni][1] = -1e9f; s_[mi][ni][3] = -1e9f; }
            }

        #pragma unroll
        for (int mi = 0; mi < 2; mi++) {
            float cm0 = -1e9f, cm1 = -1e9f;
            #pragma unroll
            for (int ni = 0; ni < 8; ni++) {
                cm0 = fmaxf(cm0, fmaxf(s_[mi][ni][0], s_[mi][ni][1]));
                cm1 = fmaxf(cm1, fmaxf(s_[mi][ni][2], s_[mi][ni][3]));
            }
            cm0 = fmaxf(cm0, __shfl_xor_sync(0xffffffffu, cm0, 1));
            cm0 = fmaxf(cm0, __shfl_xor_sync(0xffffffffu, cm0, 2));
            cm1 = fmaxf(cm1, __shfl_xor_sync(0xffffffffu, cm1, 1));
            cm1 = fmaxf(cm1, __shfl_xor_sync(0xffffffffu, cm1, 2));
            float nm0 = fmaxf(mrow[mi][0], cm0);
            float nm1 = fmaxf(mrow[mi][1], cm1);
            float c0 = __expf(mrow[mi][0] - nm0);
            float c1 = __expf(mrow[mi][1] - nm1);
            float rs0 = 0.f, rs1 = 0.f;
            #pragma unroll
            for (int ni = 0; ni < 8; ni++) {
                s_[mi][ni][0] = __expf(s_[mi][ni][0] - nm0);
                s_[mi][ni][1] = __expf(s_[mi][ni][1] - nm0);
                s_[mi][ni][2] = __expf(s_[mi][ni][2] - nm1);
                s_[mi][ni][3] = __expf(s_[mi][ni][3] - nm1);
                rs0 += s_[mi][ni][0] + s_[mi][ni][1];
                rs1 += s_[mi][ni][2] + s_[mi][ni][3];
            }
            rs0 += __shfl_xor_sync(0xffffffffu, rs0, 1);
            rs0 += __shfl_xor_sync(0xffffffffu, rs0, 2);
            rs1 += __shfl_xor_sync(0xffffffffu, rs1, 1);
            rs1 += __shfl_xor_sync(0xffffffffu, rs1, 2);
            lrow[mi][0] = lrow[mi][0] * c0 + rs0;
            lrow[mi][1] = lrow[mi][1] * c1 + rs1;
            mrow[mi][0] = nm0; mrow[mi][1] = nm1;
            #pragma unroll
            for (int ni = 0; ni < 8; ni++) {
                acc_o[mi][ni][0] *= c0; acc_o[mi][ni][1] *= c0;
                acc_o[mi][ni][2] *= c1; acc_o[mi][ni][3] *= c1;
            }
        }

        #pragma unroll
        for (int kj = 0; kj < 4; kj++) {
            uint32_t pa[2][4];
            #pragma unroll
            for (int mi = 0; mi < 2; mi++) {
                pa[mi][0] = packh2(s_[mi][2*kj][0],   s_[mi][2*kj][1]);
                pa[mi][1] = packh2(s_[mi][2*kj][2],   s_[mi][2*kj][3]);
                pa[mi][2] = packh2(s_[mi][2*kj+1][0], s_[mi][2*kj+1][1]);
                pa[mi][3] = packh2(s_[mi][2*kj+1][2], s_[mi][2*kj+1][3]);
            }
            #pragma unroll
            for (int ni = 0; ni < 8; ni++) {
                uint32_t vd = (uint32_t)(ni * 8 + (l & 7)) * VROW
                            + (uint32_t)((l >> 3) & 1) * 16u
                            + (uint32_t)kbase * 2u + (uint32_t)kj * 32u;
                uint32_t v0, v1;
                ldsm2(v0, v1, sb + SM_VT + vd);
                #pragma unroll
                for (int mi = 0; mi < 2; mi++)
                    mma_f16(acc_o[mi][ni], pa[mi], v0, v1);
            }
        }
    }

    #pragma unroll
    for (int mi = 0; mi < 2; mi++) {
        float inv0 = (lrow[mi][0] > 0.f) ? 1.f / lrow[mi][0] : 0.f;
        float inv1 = (lrow[mi][1] > 0.f) ? 1.f / lrow[mi][1] : 0.f;
        int ra = wq + mi * 16 + (l >> 2);
        int rb = ra + 8;
        #pragma unroll
        for (int ni = 0; ni < 8; ni++) {
            int col = h * DHv + ni * 8 + (l & 3) * 2;
            *(float2*)(o + ((size_t)b * Sv + ra) * Dv + col) =
                make_float2(acc_o[mi][ni][0] * inv0, acc_o[mi][ni][1] * inv0);
            *(float2*)(o + ((size_t)b * Sv + rb) * Dv + col) =
                make_float2(acc_o[mi][ni][2] * inv1, acc_o[mi][ni][3] * inv1);
        }
    }
}

// ---------------- transpose + fp16 round ----------------
__global__ void __launch_bounds__(256)
tsplit_k(const float* __restrict__ in, __half* __restrict__ outH, int R, int C)
{
    __shared__ float t[32][33];
    size_t zo = (size_t)blockIdx.z * R * C;
    int c0 = blockIdx.x * 32, r0 = blockIdx.y * 32;
    int x = threadIdx.x, y = threadIdx.y;
    #pragma unroll
    for (int i = 0; i < 32; i += 8) {
        int r = r0 + y + i, c = c0 + x;
        if (r < R && c < C) t[y + i][x] = in[zo + (size_t)r * C + c];
    }
    __syncthreads();
    #pragma unroll
    for (int i = 0; i < 32; i += 8) {
        int c = c0 + y + i, r = r0 + x;
        if (c < C && r < R)
            outH[zo + (size_t)c * R + r] = __float2half_rn(t[x][y + i]);
    }
}

// ---------------- misc helpers ----------------
__device__ __forceinline__ float blk_sum(float v, float* sbuf) {
    __syncthreads();
    int lane = threadIdx.x & 31, w = threadIdx.x >> 5;
    #pragma unroll
    for (int o = 16; o; o >>= 1) v += __shfl_xor_sync(0xffffffffu, v, o);
    if (lane == 0) sbuf[w] = v;
    __syncthreads();
    int nw = blockDim.x >> 5;
    float r = (threadIdx.x < nw) ? sbuf[threadIdx.x] : 0.f;
    if (w == 0) {
        #pragma unroll
        for (int o = 16; o; o >>= 1) r += __shfl_xor_sync(0xffffffffu, r, o);
        if (lane == 0) sbuf[0] = r;
    }
    __syncthreads();
    return sbuf[0];
}

// ---------------- embedding + positional encoding ----------------
__global__ void __launch_bounds__(128)
embed_k(const int* __restrict__ ids, const float* __restrict__ emb,
        const float* __restrict__ pe, float* __restrict__ x)
{
    int token = blockIdx.x;
    int tid = threadIdx.x;
    int s = token % Sv;
    int id = ids[token];
    float4 e = ((const float4*)(emb + (size_t)id * Dv))[tid];
    float4 p = ((const float4*)(pe + (size_t)s * Dv))[tid];
    e.x += p.x; e.y += p.y; e.z += p.z; e.w += p.w;
    ((float4*)(x + (size_t)token * Dv))[tid] = e;
}

// ---------------- LayerNorm (input already has residual added) ----------------
__global__ void __launch_bounds__(128)
ln_k(const float* __restrict__ xin, const float* __restrict__ s,
     const float* __restrict__ bta, float* __restrict__ out)
{
    __shared__ float sbuf[8];
    int row = blockIdx.x, tid = threadIdx.x;
    float4 v = ((const float4*)(xin + (size_t)row * Dv))[tid];

    float sum = blk_sum(v.x + v.y + v.z + v.w, sbuf);
    float mean = sum * (1.f / Dv);
    float dx = v.x - mean, dy = v.y - mean, dz = v.z - mean, dw = v.w - mean;
    float var = blk_sum(dx*dx + dy*dy + dz*dz + dw*dw, sbuf) * (1.f / Dv);
    float rstd = rsqrtf(var + 1e-5f);

    float4 sv = ((const float4*)s)[tid];
    float4 bv = ((const float4*)bta)[tid];
    float4 r;
    r.x = dx * rstd * sv.x + bv.x;
    r.y = dy * rstd * sv.y + bv.y;
    r.z = dz * rstd * sv.z + bv.z;
    r.w = dw * rstd * sv.w + bv.w;
    ((float4*)(out + (size_t)row * Dv))[tid] = r;
}

// ---------------- duration head ----------------
__global__ void __launch_bounds__(256)
dur_head_k(const float* __restrict__ durh, const float* __restrict__ W2,
           const float* __restrict__ b2, float* __restrict__ dur)
{
    __shared__ float sbuf[8];
    int row = blockIdx.x, tid = threadIdx.x;
    float v = durh[(size_t)row * 256 + tid] * W2[tid];
    v = blk_sum(v, sbuf);
    if (tid == 0) {
        float z = v + b2[0];
        dur[row] = (z > 20.f) ? z : log1pf(expf(z));
    }
}

// ---------------- fused cumulative durations + frame->source index ----------------
__global__ void __launch_bounds__(256)
cumidx_k(const float* __restrict__ dur, int* __restrict__ idx)
{
    __shared__ int ws[8];
    __shared__ int cums[Sv];
    int b = blockIdx.x, t = threadIdx.x;
    int lane = t & 31, w = t >> 5;
    int d = (int)rintf(dur[b * Sv + t]);
    if (d < 1) d = 1;
    int v = d;
    #pragma unroll
    for (int o = 1; o < 32; o <<= 1) {
        int u = __shfl_up_sync(0xffffffffu, v, o);
        if (lane >= o) v += u;
    }
    if (lane == 31) ws[w] = v;
    __syncthreads();
    if (t < 8) {
        int s = ws[t];
        #pragma unroll
        for (int o = 1; o < 8; o <<= 1) {
            int u = __shfl_up_sync(0x000000ffu, s, o);
            if (t >= o) s += u;
        }
        ws[t] = s;
    }
    __syncthreads();
    int off = (w > 0) ? ws[w - 1] : 0;
    cums[t] = v + off;
    __syncthreads();
    int total = cums[Sv - 1];
    #pragma unroll
    for (int i = 0; i < Tv / 256; i++) {
        int tt = t + i * 256;
        int lo = 0, hi = Sv;
        while (lo < hi) { int mid = (lo + hi) >> 1; if (cums[mid] <= tt) lo = mid + 1; else hi = mid; }
        int ix = lo > (Sv - 1) ? (Sv - 1) : lo;
        idx[b * Tv + tt] = (tt < total) ? ix : -1;
    }
}

// ---------------- mel for invalid frames ----------------
__global__ void __launch_bounds__(256)
melinv_k(const float* __restrict__ b1, const float* __restrict__ W2,
         const float* __restrict__ b2, float* __restrict__ inv)
{
    __shared__ float sbuf[8];
    int nm = blockIdx.x, tid = threadIdx.x;
    float v = 0.f;
    for (int f = tid; f < FFv; f += 256) {
        float r = b1[f]; r = r > 0.f ? r : 0.f;
        v += r * W2[(size_t)f * NMv + nm];
    }
    v = blk_sum(v, sbuf);
    if (tid == 0) inv[nm] = v + b2[nm];
}

// ---------------- gather mel rows into [B, NM, T] ----------------
__global__ void __launch_bounds__(256)
gather_k(const int* __restrict__ idx, const float* __restrict__ mels,
         const float* __restrict__ inv, float* __restrict__ mel)
{
    int t = blockIdx.x * 256 + threadIdx.x;
    int bn = blockIdx.y;
    int b = bn / NMv, nm = bn % NMv;
    int iv = idx[b * Tv + t];
    mel[(size_t)bn * Tv + t] =
        (iv < 0) ? inv[nm] : mels[((size_t)b * Sv + iv) * NMv + nm];
}

// ---------------- host launcher ----------------
static inline int gsmem(int nt) { return 3 * (2 * 128 * 80 + nt * 80); }

extern "C" void kernel_launch(void* const* d_in, const int* in_sizes, int n_in,
                              void* d_out, int out_size)
{
    const int*   ids    = (const int*)  d_in[0];
    const int*   lens   = (const int*)  d_in[1];
    const float* emb    = (const float*)d_in[3];
    const float* pe     = (const float*)d_in[4];
    const float* Wqkv   = (const float*)d_in[5];
    const float* bqkv   = (const float*)d_in[6];
    const float* Wo     = (const float*)d_in[7];
    const float* bo     = (const float*)d_in[8];
    const float* ln1s   = (const float*)d_in[9];
    const float* ln1b   = (const float*)d_in[10];
    const float* ln2s   = (const float*)d_in[11];
    const float* ln2b   = (const float*)d_in[12];
    const float* W1     = (const float*)d_in[13];
    const float* b1     = (const float*)d_in[14];
    const float* W2     = (const float*)d_in[15];
    const float* b2     = (const float*)d_in[16];
    const float* melW1  = (const float*)d_in[17];
    const float* melb1  = (const float*)d_in[18];
    const float* melW2  = (const float*)d_in[19];
    const float* melb2  = (const float*)d_in[20];
    const float* durW1  = (const float*)d_in[21];
    const float* durb1  = (const float*)d_in[22];
    const float* durW2  = (const float*)d_in[23];
    const float* durb2  = (const float*)d_in[24];

    float* out     = (float*)d_out;
    float* out_mel = out;
    float* out_dur = out + (size_t)Bv * NMv * Tv;
    float* out_enc = out_dur + (size_t)Bv * Sv;

    float *x, *qkv, *attn, *tmp, *big, *durh, *mels, *inv;
    int *idxp;
    __half *qkvT, *WoT, *W1T, *W2T, *m1T, *m2T, *d1T;
    cudaGetSymbolAddress((void**)&x,    g_x);
    cudaGetSymbolAddress((void**)&qkv,  g_qkv);
    cudaGetSymbolAddress((void**)&attn, g_attn);
    cudaGetSymbolAddress((void**)&tmp,  g_tmp);
    cudaGetSymbolAddress((void**)&big,  g_big);
    cudaGetSymbolAddress((void**)&durh, g_durh);
    cudaGetSymbolAddress((void**)&mels, g_mels);
    cudaGetSymbolAddress((void**)&inv,  g_inv);
    cudaGetSymbolAddress((void**)&idxp, g_idx);
    cudaGetSymbolAddress((void**)&qkvT, g_qkvT);
    cudaGetSymbolAddress((void**)&WoT,  g_WoT);
    cudaGetSymbolAddress((void**)&W1T,  g_W1T);
    cudaGetSymbolAddress((void**)&W2T,  g_W2T);
    cudaGetSymbolAddress((void**)&m1T,  g_m1T);
    cudaGetSymbolAddress((void**)&m2T,  g_m2T);
    cudaGetSymbolAddress((void**)&d1T,  g_d1T);

    cudaFuncSetAttribute(fattn_k, cudaFuncAttributeMaxDynamicSharedMemorySize, SM_ATT);
    const int sm64 = gsmem(64), sm128 = gsmem(128);
    cudaFuncSetAttribute(mgemm_k<64,1>,  cudaFuncAttributeMaxDynamicSharedMemorySize, sm64);
    cudaFuncSetAttribute(mgemm_k<64,2>,  cudaFuncAttributeMaxDynamicSharedMemorySize, sm64);
    cudaFuncSetAttribute(mgemm_k<64,3>,  cudaFuncAttributeMaxDynamicSharedMemorySize, sm64);
    cudaFuncSetAttribute(mgemm_k<128,2>, cudaFuncAttributeMaxDynamicSharedMemorySize, sm128);

    dim3 tb(32, 8);
    tsplit_k<<<dim3(48, 16, Lv), tb>>>(Wqkv,  qkvT, Dv, 3 * Dv);
    tsplit_k<<<dim3(16, 16, Lv), tb>>>(Wo,    WoT,  Dv, Dv);
    tsplit_k<<<dim3(64, 16, Lv), tb>>>(W1,    W1T,  Dv, FFv);
    tsplit_k<<<dim3(16, 64, Lv), tb>>>(W2,    W2T,  FFv, Dv);
    tsplit_k<<<dim3(64, 16, 1),  tb>>>(melW1, m1T,  Dv, FFv);
    tsplit_k<<<dim3(3,  64, 1),  tb>>>(melW2, m2T,  FFv, NMv);
    tsplit_k<<<dim3(8,  16, 1),  tb>>>(durW1, d1T,  Dv, 256);

    embed_k<<<NTOK, 128>>>(ids, emb, pe, x);

    for (int l = 0; l < Lv; l++) {
        mgemm_k<64,1><<<dim3(24, 32), 256, sm64>>>(
            x, qkvT + (size_t)l * 3 * Dv * Dv, bqkv + l * 3 * Dv, nullptr,
            qkv, NTOK, 3 * Dv, Dv);
        fattn_k<<<dim3(Hv, Bv), 256, SM_ATT>>>(qkv, lens, attn);
        // Wo GEMM with fused residual: tmp = x + attn@Wo + bo
        mgemm_k<64,3><<<dim3(8, 32), 256, sm64>>>(
            attn, WoT + (size_t)l * Dv * Dv, bo + l * Dv, x, tmp, NTOK, Dv, Dv);
        ln_k<<<NTOK, 128>>>(tmp, ln1s + l * Dv, ln1b + l * Dv, x);
        mgemm_k<128,2><<<dim3(16, 32), 256, sm128>>>(
            x, W1T + (size_t)l * FFv * Dv, b1 + l * FFv, nullptr,
            big, NTOK, FFv, Dv);
        // ff2 GEMM with fused residual: tmp = x + big@W2 + b2
        mgemm_k<64,3><<<dim3(8, 32), 256, sm64>>>(
            big, W2T + (size_t)l * Dv * FFv, b2 + l * Dv, x, tmp, NTOK, Dv, FFv);
        // last layer writes enc directly into the output buffer
        float* xout = (l == Lv - 1) ? out_enc : x;
        ln_k<<<NTOK, 128>>>(tmp, ln2s + l * Dv, ln2b + l * Dv, xout);
    }

    // duration head (reads enc from out_enc)
    mgemm_k<64,2><<<dim3(4, 32), 256, sm64>>>(
        out_enc, d1T, durb1, nullptr, durh, NTOK, 256, Dv);
    dur_head_k<<<NTOK, 256>>>(durh, durW2, durb2, out_dur);
    cumidx_k<<<Bv, 256>>>(out_dur, idxp);

    // mel head on source tokens (gather commutes with row-wise MLP)
    mgemm_k<128,2><<<dim3(16, 32), 256, sm128>>>(
        out_enc, m1T, melb1, nullptr, big, NTOK, FFv, Dv);
    mgemm_k<64,1><<<dim3(2, 32), 256, sm64>>>(
        big, m2T, melb2, nullptr, mels, NTOK, NMv, FFv);
    melinv_k<<<NMv, 256>>>(melb1, melW2, melb2, inv);

    gather_k<<<dim3(Tv / 256, Bv * NMv), 256>>>(idxp, mels, inv, out_mel);
}

// round 17
// speedup vs baseline: 1.0098x; 1.0098x over previous
#include <cuda_runtime.h>
#include <cuda_fp16.h>
#include <math.h>
#include <stdint.h>

// ---------------- problem constants ----------------
#define Bv   16
#define Sv   256
#define Tv   2048
#define Dv   512
#define Hv   8
#define DHv  64
#define Lv   6
#define FFv  2048
#define NMv  80
#define NTOK (Bv*Sv)            // 4096 tokens

// ---------------- scratch (no allocs allowed) ----------------
__device__ float g_x   [NTOK*Dv];
__device__ float g_qkv [NTOK*3*Dv];
__device__ float g_attn[NTOK*Dv];
__device__ float g_tmp [NTOK*Dv];
__device__ float g_big [NTOK*FFv];
__device__ float g_durh[NTOK*256];
__device__ float g_mels[NTOK*NMv];
__device__ float g_inv [NMv];
__device__ int   g_idx [Bv*Tv];
// transposed weights ([N,K] K-major, single fp16)
__device__ __half g_qkvT[Lv*3*Dv*Dv];
__device__ __half g_WoT [Lv*Dv*Dv];
__device__ __half g_W1T [Lv*FFv*Dv];
__device__ __half g_W2T [Lv*Dv*FFv];
__device__ __half g_m1T [FFv*Dv];
__device__ __half g_m2T [NMv*FFv];
__device__ __half g_d1T [256*Dv];

// ---------------- low-level helpers ----------------
__device__ __forceinline__ uint32_t smem_u32(const void* p) {
    uint32_t a;
    asm("{ .reg .u64 t; cvta.to.shared.u64 t, %1; cvt.u32.u64 %0, t; }" : "=r"(a) : "l"(p));
    return a;
}
__device__ __forceinline__ void ldsm4(uint32_t& a0, uint32_t& a1, uint32_t& a2,
                                      uint32_t& a3, uint32_t addr) {
    asm volatile("ldmatrix.sync.aligned.m8n8.x4.shared.b16 {%0,%1,%2,%3}, [%4];"
                 : "=r"(a0), "=r"(a1), "=r"(a2), "=r"(a3) : "r"(addr));
}
__device__ __forceinline__ void ldsm2(uint32_t& b0, uint32_t& b1, uint32_t addr) {
    asm volatile("ldmatrix.sync.aligned.m8n8.x2.shared.b16 {%0,%1}, [%2];"
                 : "=r"(b0), "=r"(b1) : "r"(addr));
}
__device__ __forceinline__ void mma_f16(float* c, const uint32_t* a,
                                        uint32_t b0, uint32_t b1) {
    asm volatile("mma.sync.aligned.m16n8k16.row.col.f32.f16.f16.f32 "
                 "{%0,%1,%2,%3}, {%4,%5,%6,%7}, {%8,%9}, {%0,%1,%2,%3};"
                 : "+f"(c[0]), "+f"(c[1]), "+f"(c[2]), "+f"(c[3])
                 : "r"(a[0]), "r"(a[1]), "r"(a[2]), "r"(a[3]), "r"(b0), "r"(b1));
}
__device__ __forceinline__ void cpa16(uint32_t dst, const void* src, int sz) {
    asm volatile("cp.async.cg.shared.global [%0], [%1], 16, %2;"
                 :: "r"(dst), "l"(src), "r"(sz) : "memory");
}
#define CPA_COMMIT() asm volatile("cp.async.commit_group;" ::: "memory")
#define CPA_WAIT1()  asm volatile("cp.async.wait_group 1;" ::: "memory")

// split two fp32 into packed fp16x2 hi + fp16x2 lo
__device__ __forceinline__ void split2h(float x, float y, uint32_t& hi, uint32_t& lo) {
    __half2 h = __floats2half2_rn(x, y);
    float hx = __low2float(h);
    float hy = __high2float(h);
    __half2 l2 = __floats2half2_rn(x - hx, y - hy);
    hi = *(uint32_t*)&h;
    lo = *(uint32_t*)&l2;
}
__device__ __forceinline__ uint32_t packh2(float x, float y) {
    __half2 h = __floats2half2_rn(x, y);
    return *(uint32_t*)&h;
}

// ================= split-fp16 mma.sync GEMM (2-term, 3-stage, 1 sync/iter) ======
#define RSB     80u
#define TILE_A  (128u*RSB)

template<int NT_, int EPI>
__global__ void __launch_bounds__(256, 1)
mgemm_k(const float* __restrict__ A,
        const __half* __restrict__ Bt,
        const float* __restrict__ bias, float* __restrict__ C,
        int M, int N, int K)
{
    constexpr uint32_t TILE_BN = (uint32_t)NT_ * RSB;
    constexpr uint32_t STAGE = 2u * TILE_A + TILE_BN;   // A_hi | A_lo | B
    constexpr int NI = NT_ / 16;
    extern __shared__ char smem[];
    uint32_t sb = smem_u32(smem);
    int tid = threadIdx.x, wid = tid >> 5, l = tid & 31;
    int m0 = blockIdx.y * 128, n0 = blockIdx.x * NT_;
    int wm = (wid & 3) * 32, wn = (wid >> 2) * (NT_ / 2);

    float acc[2][NI][4];
    #pragma unroll
    for (int mi = 0; mi < 2; mi++)
        #pragma unroll
        for (int ni = 0; ni < NI; ni++)
            #pragma unroll
            for (int q = 0; q < 4; q++) acc[mi][ni][q] = 0.f;

    int ar_ = tid >> 3, ac_ = tid & 7;    // A: 32 rows x 8 col-groups (x4 rows)
    int brow = tid >> 2, bch = tid & 3;   // B: cp.async row/chunk

    float4 ard[4];
    const int NT = K / 32;

    auto loadA = [&](int kt) {
        int k0 = kt * 32;
        #pragma unroll
        for (int i = 0; i < 4; i++)
            ard[i] = *(const float4*)(A + (size_t)(m0 + ar_ + i * 32) * K + k0 + ac_ * 4);
    };
    auto storeA = [&](int s) {
        char* dst = smem + (uint32_t)s * STAGE;
        #pragma unroll
        for (int i = 0; i < 4; i++) {
            uint32_t h0, h1, l0, l1;
            split2h(ard[i].x, ard[i].y, h0, l0);
            split2h(ard[i].z, ard[i].w, h1, l1);
            uint32_t off = (uint32_t)(ar_ + i * 32) * RSB + ac_ * 8u;
            *(uint2*)(dst + off)          = make_uint2(h0, h1);
            *(uint2*)(dst + TILE_A + off) = make_uint2(l0, l1);
        }
    };
    auto cpaB = [&](int kt, int s) {
        uint32_t bbase = sb + (uint32_t)s * STAGE + 2u * TILE_A;
        int k0 = kt * 32;
        #pragma unroll
        for (int i = 0; i < NT_ / 64; i++) {
            int row = brow + i * 64;
            int nr = n0 + row;
            int ok  = (nr < N) ? 16 : 0;
            int nrc = (nr < N) ? nr : 0;
            cpa16(bbase + (uint32_t)row * RSB + (uint32_t)bch * 16u,
                  Bt + (size_t)nrc * K + k0 + bch * 8, ok);
        }
    };

    // prologue: stages 0, 1
    loadA(0); storeA(0); cpaB(0, 0); CPA_COMMIT();
    if (NT > 1) { loadA(1); storeA(1); cpaB(1, 1); }
    CPA_COMMIT();

    uint32_t aoff = (uint32_t)(wm + (l & 15)) * RSB + (uint32_t)(l >> 4) * 16u;
    uint32_t boff = (uint32_t)(wn + (l & 7)) * RSB + (uint32_t)((l >> 3) & 1) * 16u;

    int s_cur = 0, s_pf = 2;   // stage being computed / stage being prefetched
    for (int kt = 0; kt < NT; kt++) {
        CPA_WAIT1();
        __syncthreads();
        bool pf = (kt + 2 < NT);
        if (pf) { loadA(kt + 2); cpaB(kt + 2, s_pf); }
        CPA_COMMIT();

        // compute on stage s_cur
        {
            uint32_t aH_ = sb + (uint32_t)s_cur * STAGE;
            uint32_t aL_ = aH_ + TILE_A;
            uint32_t bB_ = aH_ + 2 * TILE_A;
            #pragma unroll
            for (int ks = 0; ks < 2; ks++) {
                uint32_t ah[2][4], al[2][4];
                #pragma unroll
                for (int mi = 0; mi < 2; mi++) {
                    uint32_t ad = aoff + (uint32_t)mi * 16u * RSB + (uint32_t)ks * 32u;
                    ldsm4(ah[mi][0], ah[mi][1], ah[mi][2], ah[mi][3], aH_ + ad);
                    ldsm4(al[mi][0], al[mi][1], al[mi][2], al[mi][3], aL_ + ad);
                }
                #pragma unroll
                for (int ni = 0; ni < NI; ni++) {
                    uint32_t bd = boff + (uint32_t)ni * 8u * RSB + (uint32_t)ks * 32u;
                    uint32_t b0, b1;
                    ldsm2(b0, b1, bB_ + bd);
                    #pragma unroll
                    for (int mi = 0; mi < 2; mi++) {
                        mma_f16(acc[mi][ni], ah[mi], b0, b1);
                        mma_f16(acc[mi][ni], al[mi], b0, b1);
                    }
                }
            }
        }
        if (pf) storeA(s_pf);
        s_cur = (s_cur == 2) ? 0 : s_cur + 1;
        s_pf  = (s_pf  == 2) ? 0 : s_pf  + 1;
    }

    // epilogue
    int r_lo = l >> 2, cpair = (l & 3) * 2;
    #pragma unroll
    for (int mi = 0; mi < 2; mi++) {
        int gr0 = m0 + wm + mi * 16 + r_lo;
        #pragma unroll
        for (int ni = 0; ni < NI; ni++) {
            int gc = n0 + wn + ni * 8 + cpair;
            if (gc < N) {
                float b0 = 0.f, b1 = 0.f;
                if (EPI >= 1) { b0 = bias[gc]; b1 = bias[gc + 1]; }
                float v0 = acc[mi][ni][0] + b0, v1 = acc[mi][ni][1] + b1;
                float v2 = acc[mi][ni][2] + b0, v3 = acc[mi][ni][3] + b1;
                if (EPI == 2) {
                    v0 = fmaxf(v0, 0.f); v1 = fmaxf(v1, 0.f);
                    v2 = fmaxf(v2, 0.f); v3 = fmaxf(v3, 0.f);
                }
                *(float2*)(C + (size_t)gr0 * N + gc)       = make_float2(v0, v1);
                *(float2*)(C + (size_t)(gr0 + 8) * N + gc) = make_float2(v2, v3);
            }
        }
    }
}

// ================= tensor-core flash attention ==================================
#define QROW 144u
#define VROW 528u
#define SM_QH 0u
#define SM_QL 36864u
#define SM_KH 73728u
#define SM_KL 110592u
#define SM_VT 147456u
#define SM_ATT (147456 + 64*528)

__global__ void __launch_bounds__(256, 1)
fattn_k(const float* __restrict__ qkv, const int* __restrict__ lens,
        float* __restrict__ o)
{
    extern __shared__ char smem[];
    uint32_t sb = smem_u32(smem);
    int h = blockIdx.x, b = blockIdx.y;
    int tid = threadIdx.x, wid = tid >> 5, l = tid & 31;
    int len = lens[b];

    {
        const float* base = qkv + (size_t)b * Sv * (3 * Dv);
        const float4* qrow = (const float4*)(base + (size_t)tid * 3 * Dv + h * DHv);
        const float4* krow = (const float4*)(base + (size_t)tid * 3 * Dv + Dv + h * DHv);
        const float4* vrow = (const float4*)(base + (size_t)tid * 3 * Dv + 2 * Dv + h * DHv);
        uint32_t qd = (uint32_t)tid * QROW;
        #pragma unroll
        for (int i = 0; i < 16; i++) {
            float4 q = qrow[i];
            q.x *= 0.125f; q.y *= 0.125f; q.z *= 0.125f; q.w *= 0.125f;
            uint32_t h0, h1, l0, l1;
            split2h(q.x, q.y, h0, l0);
            split2h(q.z, q.w, h1, l1);
            *(uint2*)(smem + qd + SM_QH + i * 8u) = make_uint2(h0, h1);
            *(uint2*)(smem + qd + SM_QL + i * 8u) = make_uint2(l0, l1);
            float4 k = krow[i];
            split2h(k.x, k.y, h0, l0);
            split2h(k.z, k.w, h1, l1);
            *(uint2*)(smem + qd + SM_KH + i * 8u) = make_uint2(h0, h1);
            *(uint2*)(smem + qd + SM_KL + i * 8u) = make_uint2(l0, l1);
            float4 v = vrow[i];
            __half* vt = (__half*)(smem + SM_VT);
            vt[(4*i+0) * (VROW/2) + tid] = __float2half_rn(v.x);
            vt[(4*i+1) * (VROW/2) + tid] = __float2half_rn(v.y);
            vt[(4*i+2) * (VROW/2) + tid] = __float2half_rn(v.z);
            vt[(4*i+3) * (VROW/2) + tid] = __float2half_rn(v.w);
        }
    }
    __syncthreads();

    int wq = wid * 32;
    float mrow[2][2], lrow[2][2];
    #pragma unroll
    for (int mi = 0; mi < 2; mi++) { mrow[mi][0] = -1e9f; mrow[mi][1] = -1e9f;
                                     lrow[mi][0] = 0.f;   lrow[mi][1] = 0.f; }
    float acc_o[2][8][4];
    #pragma unroll
    for (int mi = 0; mi < 2; mi++)
        #pragma unroll
        for (int ni = 0; ni < 8; ni++)
            #pragma unroll
            for (int q = 0; q < 4; q++) acc_o[mi][ni][q] = 0.f;

    for (int kc = 0; kc < 4; kc++) {
        int kbase = kc * 64;
        if (kbase >= len) break;

        float s_[2][8][4];
        #pragma unroll
        for (int mi = 0; mi < 2; mi++)
            #pragma unroll
            for (int ni = 0; ni < 8; ni++)
                #pragma unroll
                for (int q = 0; q < 4; q++) s_[mi][ni][q] = 0.f;

        #pragma unroll
        for (int kst = 0; kst < 4; kst++) {
            uint32_t qh[2][4], ql[2][4];
            #pragma unroll
            for (int mi = 0; mi < 2; mi++) {
                uint32_t ad = (uint32_t)(wq + mi * 16 + (l & 15)) * QROW
                            + (uint32_t)(l >> 4) * 16u + (uint32_t)kst * 32u;
                ldsm4(qh[mi][0], qh[mi][1], qh[mi][2], qh[mi][3], sb + SM_QH + ad);
                ldsm4(ql[mi][0], ql[mi][1], ql[mi][2], ql[mi][3], sb + SM_QL + ad);
            }
            #pragma unroll
            for (int ni = 0; ni < 8; ni++) {
                uint32_t kd = (uint32_t)(kbase + ni * 8 + (l & 7)) * QROW
                            + (uint32_t)((l >> 3) & 1) * 16u + (uint32_t)kst * 32u;
                uint32_t kh0, kh1, kl0, kl1;
                ldsm2(kh0, kh1, sb + SM_KH + kd);
                ldsm2(kl0, kl1, sb + SM_KL + kd);
                #pragma unroll
                for (int mi = 0; mi < 2; mi++) {
                    mma_f16(s_[mi][ni], qh[mi], kh0, kh1);
                    mma_f16(s_[mi][ni], ql[mi], kh0, kh1);
                    mma_f16(s_[mi][ni], qh[mi], kl0, kl1);
                }
            }
        }

        int kcol = kbase + (l & 3) * 2;
        #pragma unroll
        for (int mi = 0; mi < 2; mi++)
            #pragma unroll
            for (int ni = 0; ni < 8; ni++) {
                int k0 = kcol + ni * 8;
                if (k0 >= len)     { s_[mi][ni][0] = -1e9f; s_[mi][ni][2] = -1e9f; }
                if (k0 + 1 >= len) { s_[mi][ni][1] = -1e9f; s_[mi][ni][3] = -1e9f; }
            }

        #pragma unroll
        for (int mi = 0; mi < 2; mi++) {
            float cm0 = -1e9f, cm1 = -1e9f;
            #pragma unroll
            for (int ni = 0; ni < 8; ni++) {
                cm0 = fmaxf(cm0, fmaxf(s_[mi][ni][0], s_[mi][ni][1]));
                cm1 = fmaxf(cm1, fmaxf(s_[mi][ni][2], s_[mi][ni][3]));
            }
            cm0 = fmaxf(cm0, __shfl_xor_sync(0xffffffffu, cm0, 1));
            cm0 = fmaxf(cm0, __shfl_xor_sync(0xffffffffu, cm0, 2));
            cm1 = fmaxf(cm1, __shfl_xor_sync(0xffffffffu, cm1, 1));
            cm1 = fmaxf(cm1, __shfl_xor_sync(0xffffffffu, cm1, 2));
            float nm0 = fmaxf(mrow[mi][0], cm0);
            float nm1 = fmaxf(mrow[mi][1], cm1);
            float c0 = __expf(mrow[mi][0] - nm0);
            float c1 = __expf(mrow[mi][1] - nm1);
            float rs0 = 0.f, rs1 = 0.f;
            #pragma unroll
            for (int ni = 0; ni < 8; ni++) {
                s_[mi][ni][0] = __expf(s_[mi][ni][0] - nm0);
                s_[mi][ni][1] = __expf(s_[mi][ni][1] - nm0);
                s_[mi][ni][2] = __expf(s_[mi][ni][2] - nm1);
                s_[mi][ni][3] = __expf(s_[mi][ni][3] - nm1);
                rs0 += s_[mi][ni][0] + s_[mi][ni][1];
                rs1 += s_[mi][ni][2] + s_[mi][ni][3];
            }
            rs0 += __shfl_xor_sync(0xffffffffu, rs0, 1);
            rs0 += __shfl_xor_sync(0xffffffffu, rs0, 2);
            rs1 += __shfl_xor_sync(0xffffffffu, rs1, 1);
            rs1 += __shfl_xor_sync(0xffffffffu, rs1, 2);
            lrow[mi][0] = lrow[mi][0] * c0 + rs0;
            lrow[mi][1] = lrow[mi][1] * c1 + rs1;
            mrow[mi][0] = nm0; mrow[mi][1] = nm1;
            #pragma unroll
            for (int ni = 0; ni < 8; ni++) {
                acc_o[mi][ni][0] *= c0; acc_o[mi][ni][1] *= c0;
                acc_o[mi][ni][2] *= c1; acc_o[mi][ni][3] *= c1;
            }
        }

        #pragma unroll
        for (int kj = 0; kj < 4; kj++) {
            uint32_t pa[2][4];
            #pragma unroll
            for (int mi = 0; mi < 2; mi++) {
                pa[mi][0] = packh2(s_[mi][2*kj][0],   s_[mi][2*kj][1]);
                pa[mi][1] = packh2(s_[mi][2*kj][2],   s_[mi][2*kj][3]);
                pa[mi][2] = packh2(s_[mi][2*kj+1][0], s_[mi][2*kj+1][1]);
                pa[mi][3] = packh2(s_[mi][2*kj+1][2], s_[mi][2*kj+1][3]);
            }
            #pragma unroll
            for (int ni = 0; ni < 8; ni++) {
                uint32_t vd = (uint32_t)(ni * 8 + (l & 7)) * VROW
                            + (uint32_t)((l >> 3) & 1) * 16u
                            + (uint32_t)kbase * 2u + (uint32_t)kj * 32u;
                uint32_t v0, v1;
                ldsm2(v0, v1, sb + SM_VT + vd);
                #pragma unroll
                for (int mi = 0; mi < 2; mi++)
                    mma_f16(acc_o[mi][ni], pa[mi], v0, v1);
            }
        }
    }

    #pragma unroll
    for (int mi = 0; mi < 2; mi++) {
        float inv0 = (lrow[mi][0] > 0.f) ? 1.f / lrow[mi][0] : 0.f;
        float inv1 = (lrow[mi][1] > 0.f) ? 1.f / lrow[mi][1] : 0.f;
        int ra = wq + mi * 16 + (l >> 2);
        int rb = ra + 8;
        #pragma unroll
        for (int ni = 0; ni < 8; ni++) {
            int col = h * DHv + ni * 8 + (l & 3) * 2;
            *(float2*)(o + ((size_t)b * Sv + ra) * Dv + col) =
                make_float2(acc_o[mi][ni][0] * inv0, acc_o[mi][ni][1] * inv0);
            *(float2*)(o + ((size_t)b * Sv + rb) * Dv + col) =
                make_float2(acc_o[mi][ni][2] * inv1, acc_o[mi][ni][3] * inv1);
        }
    }
}

// ---------------- transpose + fp16 round ----------------
__global__ void __launch_bounds__(256)
tsplit_k(const float* __restrict__ in, __half* __restrict__ outH, int R, int C)
{
    __shared__ float t[32][33];
    size_t zo = (size_t)blockIdx.z * R * C;
    int c0 = blockIdx.x * 32, r0 = blockIdx.y * 32;
    int x = threadIdx.x, y = threadIdx.y;
    #pragma unroll
    for (int i = 0; i < 32; i += 8) {
        int r = r0 + y + i, c = c0 + x;
        if (r < R && c < C) t[y + i][x] = in[zo + (size_t)r * C + c];
    }
    __syncthreads();
    #pragma unroll
    for (int i = 0; i < 32; i += 8) {
        int c = c0 + y + i, r = r0 + x;
        if (c < C && r < R)
            outH[zo + (size_t)c * R + r] = __float2half_rn(t[x][y + i]);
    }
}

// ---------------- misc helpers ----------------
__device__ __forceinline__ float blk_sum(float v, float* sbuf) {
    __syncthreads();
    int lane = threadIdx.x & 31, w = threadIdx.x >> 5;
    #pragma unroll
    for (int o = 16; o; o >>= 1) v += __shfl_xor_sync(0xffffffffu, v, o);
    if (lane == 0) sbuf[w] = v;
    __syncthreads();
    int nw = blockDim.x >> 5;
    float r = (threadIdx.x < nw) ? sbuf[threadIdx.x] : 0.f;
    if (w == 0) {
        #pragma unroll
        for (int o = 16; o; o >>= 1) r += __shfl_xor_sync(0xffffffffu, r, o);
        if (lane == 0) sbuf[0] = r;
    }
    __syncthreads();
    return sbuf[0];
}

// ---------------- embedding + positional encoding ----------------
__global__ void __launch_bounds__(128)
embed_k(const int* __restrict__ ids, const float* __restrict__ emb,
        const float* __restrict__ pe, float* __restrict__ x)
{
    int token = blockIdx.x;
    int tid = threadIdx.x;
    int s = token % Sv;
    int id = ids[token];
    float4 e = ((const float4*)(emb + (size_t)id * Dv))[tid];
    float4 p = ((const float4*)(pe + (size_t)s * Dv))[tid];
    e.x += p.x; e.y += p.y; e.z += p.z; e.w += p.w;
    ((float4*)(x + (size_t)token * Dv))[tid] = e;
}

// ---------------- residual add + LayerNorm ----------------
__global__ void __launch_bounds__(128)
add_ln_k(const float* __restrict__ x, const float* __restrict__ y,
         const float* __restrict__ s, const float* __restrict__ bta,
         float* __restrict__ out)
{
    __shared__ float sbuf[8];
    int row = blockIdx.x, tid = threadIdx.x;
    float4 v = ((const float4*)(x + (size_t)row * Dv))[tid];
    float4 w = ((const float4*)(y + (size_t)row * Dv))[tid];
    v.x += w.x; v.y += w.y; v.z += w.z; v.w += w.w;

    float sum = blk_sum(v.x + v.y + v.z + v.w, sbuf);
    float mean = sum * (1.f / Dv);
    float dx = v.x - mean, dy = v.y - mean, dz = v.z - mean, dw = v.w - mean;
    float var = blk_sum(dx*dx + dy*dy + dz*dz + dw*dw, sbuf) * (1.f / Dv);
    float rstd = rsqrtf(var + 1e-5f);

    float4 sv = ((const float4*)s)[tid];
    float4 bv = ((const float4*)bta)[tid];
    float4 r;
    r.x = dx * rstd * sv.x + bv.x;
    r.y = dy * rstd * sv.y + bv.y;
    r.z = dz * rstd * sv.z + bv.z;
    r.w = dw * rstd * sv.w + bv.w;
    ((float4*)(out + (size_t)row * Dv))[tid] = r;
}

// ---------------- duration head ----------------
__global__ void __launch_bounds__(256)
dur_head_k(const float* __restrict__ durh, const float* __restrict__ W2,
           const float* __restrict__ b2, float* __restrict__ dur)
{
    __shared__ float sbuf[8];
    int row = blockIdx.x, tid = threadIdx.x;
    float v = durh[(size_t)row * 256 + tid] * W2[tid];
    v = blk_sum(v, sbuf);
    if (tid == 0) {
        float z = v + b2[0];
        dur[row] = (z > 20.f) ? z : log1pf(expf(z));
    }
}

// ---------------- fused cumulative durations + frame->source index ----------------
__global__ void __launch_bounds__(256)
cumidx_k(const float* __restrict__ dur, int* __restrict__ idx)
{
    __shared__ int ws[8];
    __shared__ int cums[Sv];
    int b = blockIdx.x, t = threadIdx.x;
    int lane = t & 31, w = t >> 5;
    int d = (int)rintf(dur[b * Sv + t]);
    if (d < 1) d = 1;
    int v = d;
    #pragma unroll
    for (int o = 1; o < 32; o <<= 1) {
        int u = __shfl_up_sync(0xffffffffu, v, o);
        if (lane >= o) v += u;
    }
    if (lane == 31) ws[w] = v;
    __syncthreads();
    if (t < 8) {
        int s = ws[t];
        #pragma unroll
        for (int o = 1; o < 8; o <<= 1) {
            int u = __shfl_up_sync(0x000000ffu, s, o);
            if (t >= o) s += u;
        }
        ws[t] = s;
    }
    __syncthreads();
    int off = (w > 0) ? ws[w - 1] : 0;
    cums[t] = v + off;
    __syncthreads();
    int total = cums[Sv - 1];
    #pragma unroll
    for (int i = 0; i < Tv / 256; i++) {
        int tt = t + i * 256;
        int lo = 0, hi = Sv;
        while (lo < hi) { int mid = (lo + hi) >> 1; if (cums[mid] <= tt) lo = mid + 1; else hi = mid; }
        int ix = lo > (Sv - 1) ? (Sv - 1) : lo;
        idx[b * Tv + tt] = (tt < total) ? ix : -1;
    }
}

// ---------------- mel for invalid frames ----------------
__global__ void __launch_bounds__(256)
melinv_k(const float* __restrict__ b1, const float* __restrict__ W2,
         const float* __restrict__ b2, float* __restrict__ inv)
{
    __shared__ float sbuf[8];
    int nm = blockIdx.x, tid = threadIdx.x;
    float v = 0.f;
    for (int f = tid; f < FFv; f += 256) {
        float r = b1[f]; r = r > 0.f ? r : 0.f;
        v += r * W2[(size_t)f * NMv + nm];
    }
    v = blk_sum(v, sbuf);
    if (tid == 0) inv[nm] = v + b2[nm];
}

// ---------------- gather mel rows into [B, NM, T] ----------------
__global__ void __launch_bounds__(256)
gather_k(const int* __restrict__ idx, const float* __restrict__ mels,
         const float* __restrict__ inv, float* __restrict__ mel)
{
    int t = blockIdx.x * 256 + threadIdx.x;
    int bn = blockIdx.y;
    int b = bn / NMv, nm = bn % NMv;
    int iv = idx[b * Tv + t];
    mel[(size_t)bn * Tv + t] =
        (iv < 0) ? inv[nm] : mels[((size_t)b * Sv + iv) * NMv + nm];
}

// ---------------- host launcher ----------------
static inline int gsmem(int nt) { return 3 * (2 * 128 * 80 + nt * 80); }

extern "C" void kernel_launch(void* const* d_in, const int* in_sizes, int n_in,
                              void* d_out, int out_size)
{
    const int*   ids    = (const int*)  d_in[0];
    const int*   lens   = (const int*)  d_in[1];
    const float* emb    = (const float*)d_in[3];
    const float* pe     = (const float*)d_in[4];
    const float* Wqkv   = (const float*)d_in[5];
    const float* bqkv   = (const float*)d_in[6];
    const float* Wo     = (const float*)d_in[7];
    const float* bo     = (const float*)d_in[8];
    const float* ln1s   = (const float*)d_in[9];
    const float* ln1b   = (const float*)d_in[10];
    const float* ln2s   = (const float*)d_in[11];
    const float* ln2b   = (const float*)d_in[12];
    const float* W1     = (const float*)d_in[13];
    const float* b1     = (const float*)d_in[14];
    const float* W2     = (const float*)d_in[15];
    const float* b2     = (const float*)d_in[16];
    const float* melW1  = (const float*)d_in[17];
    const float* melb1  = (const float*)d_in[18];
    const float* melW2  = (const float*)d_in[19];
    const float* melb2  = (const float*)d_in[20];
    const float* durW1  = (const float*)d_in[21];
    const float* durb1  = (const float*)d_in[22];
    const float* durW2  = (const float*)d_in[23];
    const float* durb2  = (const float*)d_in[24];

    float* out     = (float*)d_out;
    float* out_mel = out;
    float* out_dur = out + (size_t)Bv * NMv * Tv;
    float* out_enc = out_dur + (size_t)Bv * Sv;

    float *x, *qkv, *attn, *tmp, *big, *durh, *mels, *inv;
    int *idxp;
    __half *qkvT, *WoT, *W1T, *W2T, *m1T, *m2T, *d1T;
    cudaGetSymbolAddress((void**)&x,    g_x);
    cudaGetSymbolAddress((void**)&qkv,  g_qkv);
    cudaGetSymbolAddress((void**)&attn, g_attn);
    cudaGetSymbolAddress((void**)&tmp,  g_tmp);
    cudaGetSymbolAddress((void**)&big,  g_big);
    cudaGetSymbolAddress((void**)&durh, g_durh);
    cudaGetSymbolAddress((void**)&mels, g_mels);
    cudaGetSymbolAddress((void**)&inv,  g_inv);
    cudaGetSymbolAddress((void**)&idxp, g_idx);
    cudaGetSymbolAddress((void**)&qkvT, g_qkvT);
    cudaGetSymbolAddress((void**)&WoT,  g_WoT);
    cudaGetSymbolAddress((void**)&W1T,  g_W1T);
    cudaGetSymbolAddress((void**)&W2T,  g_W2T);
    cudaGetSymbolAddress((void**)&m1T,  g_m1T);
    cudaGetSymbolAddress((void**)&m2T,  g_m2T);
    cudaGetSymbolAddress((void**)&d1T,  g_d1T);

    cudaFuncSetAttribute(fattn_k, cudaFuncAttributeMaxDynamicSharedMemorySize, SM_ATT);
    const int sm64 = gsmem(64), sm128 = gsmem(128);
    cudaFuncSetAttribute(mgemm_k<64,1>,  cudaFuncAttributeMaxDynamicSharedMemorySize, sm64);
    cudaFuncSetAttribute(mgemm_k<64,2>,  cudaFuncAttributeMaxDynamicSharedMemorySize, sm64);
    cudaFuncSetAttribute(mgemm_k<128,2>, cudaFuncAttributeMaxDynamicSharedMemorySize, sm128);

    dim3 tb(32, 8);
    tsplit_k<<<dim3(48, 16, Lv), tb>>>(Wqkv,  qkvT, Dv, 3 * Dv);
    tsplit_k<<<dim3(16, 16, Lv), tb>>>(Wo,    WoT,  Dv, Dv);
    tsplit_k<<<dim3(64, 16, Lv), tb>>>(W1,    W1T,  Dv, FFv);
    tsplit_k<<<dim3(16, 64, Lv), tb>>>(W2,    W2T,  FFv, Dv);
    tsplit_k<<<dim3(64, 16, 1),  tb>>>(melW1, m1T,  Dv, FFv);
    tsplit_k<<<dim3(3,  64, 1),  tb>>>(melW2, m2T,  FFv, NMv);
    tsplit_k<<<dim3(8,  16, 1),  tb>>>(durW1, d1T,  Dv, 256);

    embed_k<<<NTOK, 128>>>(ids, emb, pe, x);

    for (int l = 0; l < Lv; l++) {
        mgemm_k<64,1><<<dim3(24, 32), 256, sm64>>>(
            x, qkvT + (size_t)l * 3 * Dv * Dv, bqkv + l * 3 * Dv, qkv, NTOK, 3 * Dv, Dv);
        fattn_k<<<dim3(Hv, Bv), 256, SM_ATT>>>(qkv, lens, attn);
        mgemm_k<64,1><<<dim3(8, 32), 256, sm64>>>(
            attn, WoT + (size_t)l * Dv * Dv, bo + l * Dv, tmp, NTOK, Dv, Dv);
        add_ln_k<<<NTOK, 128>>>(x, tmp, ln1s + l * Dv, ln1b + l * Dv, x);
        mgemm_k<128,2><<<dim3(16, 32), 256, sm128>>>(
            x, W1T + (size_t)l * FFv * Dv, b1 + l * FFv, big, NTOK, FFv, Dv);
        mgemm_k<64,1><<<dim3(8, 32), 256, sm64>>>(
            big, W2T + (size_t)l * Dv * FFv, b2 + l * Dv, tmp, NTOK, Dv, FFv);
        // last layer writes enc directly into the output buffer
        float* xout = (l == Lv - 1) ? out_enc : x;
        add_ln_k<<<NTOK, 128>>>(x, tmp, ln2s + l * Dv, ln2b + l * Dv, xout);
    }

    // duration head (reads enc from out_enc)
    mgemm_k<64,2><<<dim3(4, 32), 256, sm64>>>(out_enc, d1T, durb1, durh, NTOK, 256, Dv);
    dur_head_k<<<NTOK, 256>>>(durh, durW2, durb2, out_dur);
    cumidx_k<<<Bv, 256>>>(out_dur, idxp);

    // mel head on source tokens (gather commutes with row-wise MLP)
    mgemm_k<128,2><<<dim3(16, 32), 256, sm128>>>(out_enc, m1T, melb1, big, NTOK, FFv, Dv);
    mgemm_k<64,1><<<dim3(2, 32), 256, sm64>>>(big, m2T, melb2, mels, NTOK, NMv, FFv);
    melinv_k<<<NMv, 256>>>(melb1, melW2, melb2, inv);

    gather_k<<<dim3(Tv / 256, Bv * NMv), 256>>>(idxp, mels, inv, out_mel);
}